// round 2
// baseline (speedup 1.0000x reference)
#include <cuda_runtime.h>
#include <math.h>

#define N 4096
#define D 512
#define NT (N / 128)

// ---------------- device scratch (no allocations allowed) ----------------
__device__ float g_zn1[N * D];
__device__ float g_zn2[N * D];

// Accumulator layout (all row-indexed, length N each):
//  off  0*N : sI1  [3]  sum exp(S11/tau) for tau {0.8,0.72,0.64}
//  off  3*N : sX12 [3]  sum exp(S12/tau)
//  off  6*N : sI2  [3]  sum exp(S22/tau)
//  off  9*N : sX21 [3]  sum exp(S21/tau)
//  off 12*N : wI1  [5]  adj-weighted S11 sums  (c*e0, m*e0, f*e0, c*e2, m*e1)
//  off 17*N : wX12 [5]  adj-weighted S12 sums  (same pairs)
//  off 22*N : wI2  [5]  aug-weighted S22 sums  (c*e0, m*e0, f*e0, f*e2, f*e1)
//  off 27*N : wX21 [5]  aug-weighted S21 sums  (same pairs)
//  off 32*N : rA   [3]  adj row sums (c,m,f)
//  off 35*N : rG   [3]  aug row sums (c,m,f)
//  off 38*N : d11, 39*N : d22, 40*N : d12
#define ACC_TOTAL (41 * N)
__device__ float g_acc[ACC_TOTAL];

// ---------------- kernels ----------------
__global__ void zero_acc_kernel() {
    int i = blockIdx.x * blockDim.x + threadIdx.x;
    if (i < ACC_TOTAL) g_acc[i] = 0.0f;
}

// One block per row; blockIdx.y selects z1/z2. 128 threads, 4 floats each.
__global__ void normalize_kernel(const float* __restrict__ z1,
                                 const float* __restrict__ z2) {
    int row = blockIdx.x;
    const float* src = (blockIdx.y == 0) ? z1 : z2;
    float* dst = (blockIdx.y == 0) ? g_zn1 : g_zn2;
    int t = threadIdx.x;

    float4 v = ((const float4*)(src + (size_t)row * D))[t];
    float s = v.x * v.x + v.y * v.y + v.z * v.z + v.w * v.w;
#pragma unroll
    for (int o = 16; o; o >>= 1) s += __shfl_xor_sync(0xffffffffu, s, o);

    __shared__ float ws[4];
    if ((t & 31) == 0) ws[t >> 5] = s;
    __syncthreads();
    float tot = ws[0] + ws[1] + ws[2] + ws[3];
    float inv = 1.0f / fmaxf(sqrtf(tot), 1e-12f);
    float4 o4 = make_float4(v.x * inv, v.y * inv, v.z * inv, v.w * inv);
    ((float4*)(dst + (size_t)row * D))[t] = o4;
}

__device__ __forceinline__ float red16(float v) {
#pragma unroll
    for (int o = 8; o; o >>= 1) v += __shfl_xor_sync(0xffffffffu, v, o);
    return v;
}

// 128x128 tile per CTA; 4 sequential Gram passes (S11,S22,S12,S21) with
// fused exp + adjacency-weighted row reductions.
__global__ __launch_bounds__(256, 2)
void gram_kernel(const float* __restrict__ adj_c, const float* __restrict__ adj_m,
                 const float* __restrict__ adj_f, const float* __restrict__ aug_c,
                 const float* __restrict__ aug_m, const float* __restrict__ aug_f) {
    __shared__ float As[16][128];
    __shared__ float Bs[16][128];

    const int tid = threadIdx.x;
    const int tx = tid & 15;
    const int ty = tid >> 4;
    const int I = blockIdx.y;
    const int J = blockIdx.x;

    const float INV_T0 = 1.0f / 0.8f;
    const float INV_T1 = 1.0f / 0.72f;
    const float INV_T2 = 1.0f / 0.64f;

    for (int pass = 0; pass < 4; ++pass) {
        const float *A, *B, *a0p, *a1p, *a2p;
        float *sSum, *wSum, *rowSum = nullptr, *diagDst = nullptr;
        bool adjType;
        switch (pass) {
            case 0:
                A = g_zn1; B = g_zn1; a0p = adj_c; a1p = adj_m; a2p = adj_f;
                sSum = g_acc + 0 * N; wSum = g_acc + 12 * N;
                rowSum = g_acc + 32 * N; diagDst = g_acc + 38 * N; adjType = true;
                break;
            case 1:
                A = g_zn2; B = g_zn2; a0p = aug_c; a1p = aug_m; a2p = aug_f;
                sSum = g_acc + 6 * N; wSum = g_acc + 22 * N;
                rowSum = g_acc + 35 * N; diagDst = g_acc + 39 * N; adjType = false;
                break;
            case 2:
                A = g_zn1; B = g_zn2; a0p = adj_c; a1p = adj_m; a2p = adj_f;
                sSum = g_acc + 3 * N; wSum = g_acc + 17 * N;
                diagDst = g_acc + 40 * N; adjType = true;
                break;
            default:
                A = g_zn2; B = g_zn1; a0p = aug_c; a1p = aug_m; a2p = aug_f;
                sSum = g_acc + 9 * N; wSum = g_acc + 27 * N; adjType = false;
                break;
        }

        float acc[8][8];
#pragma unroll
        for (int i = 0; i < 8; i++)
#pragma unroll
            for (int j = 0; j < 8; j++) acc[i][j] = 0.0f;

        const float* Abase = A + (size_t)I * 128 * D;
        const float* Bbase = B + (size_t)J * 128 * D;

        for (int kt = 0; kt < D; kt += 16) {
#pragma unroll
            for (int u = 0; u < 2; u++) {
                int idx = tid + u * 256;          // 0..511 float4 slots
                int row = idx >> 2;               // 0..127
                int c4 = idx & 3;                 // 0..3
                float4 av = *(const float4*)(Abase + (size_t)row * D + kt + c4 * 4);
                As[c4 * 4 + 0][row] = av.x;
                As[c4 * 4 + 1][row] = av.y;
                As[c4 * 4 + 2][row] = av.z;
                As[c4 * 4 + 3][row] = av.w;
                float4 bv = *(const float4*)(Bbase + (size_t)row * D + kt + c4 * 4);
                Bs[c4 * 4 + 0][row] = bv.x;
                Bs[c4 * 4 + 1][row] = bv.y;
                Bs[c4 * 4 + 2][row] = bv.z;
                Bs[c4 * 4 + 3][row] = bv.w;
            }
            __syncthreads();
#pragma unroll
            for (int kk = 0; kk < 16; kk++) {
                float a[8], b[8];
#pragma unroll
                for (int i = 0; i < 8; i++) a[i] = As[kk][ty * 8 + i];
#pragma unroll
                for (int j = 0; j < 8; j++) b[j] = Bs[kk][tx * 8 + j];
#pragma unroll
                for (int i = 0; i < 8; i++)
#pragma unroll
                    for (int j = 0; j < 8; j++) acc[i][j] += a[i] * b[j];
            }
            __syncthreads();
        }

        // ---- fused epilogue: exps + adjacency-weighted row reductions ----
        const int rowg0 = I * 128 + ty * 8;
        const int colg0 = J * 128 + tx * 8;
#pragma unroll
        for (int r = 0; r < 8; r++) {
            const int rowg = rowg0 + r;
            const size_t base = (size_t)rowg * N + colg0;
            float a0v[8], a1v[8], a2v[8];
            *(float4*)&a0v[0] = *(const float4*)(a0p + base);
            *(float4*)&a0v[4] = *(const float4*)(a0p + base + 4);
            *(float4*)&a1v[0] = *(const float4*)(a1p + base);
            *(float4*)&a1v[4] = *(const float4*)(a1p + base + 4);
            *(float4*)&a2v[0] = *(const float4*)(a2p + base);
            *(float4*)&a2v[4] = *(const float4*)(a2p + base + 4);

            float e0s = 0.f, e1s = 0.f, e2s = 0.f;
            float w0 = 0.f, w1 = 0.f, w2 = 0.f, w3 = 0.f, w4 = 0.f;
            float r0 = 0.f, r1 = 0.f, r2 = 0.f;
#pragma unroll
            for (int c = 0; c < 8; c++) {
                float s = acc[r][c];
                float e0 = __expf(s * INV_T0);
                float e1 = __expf(s * INV_T1);
                float e2 = __expf(s * INV_T2);
                e0s += e0; e1s += e1; e2s += e2;
                w0 += a0v[c] * e0;
                w1 += a1v[c] * e0;
                w2 += a2v[c] * e0;
                if (adjType) { w3 += a0v[c] * e2; w4 += a1v[c] * e1; }
                else         { w3 += a2v[c] * e2; w4 += a2v[c] * e1; }
                r0 += a0v[c]; r1 += a1v[c]; r2 += a2v[c];
            }
            e0s = red16(e0s); e1s = red16(e1s); e2s = red16(e2s);
            w0 = red16(w0); w1 = red16(w1); w2 = red16(w2);
            w3 = red16(w3); w4 = red16(w4);
            if (rowSum) { r0 = red16(r0); r1 = red16(r1); r2 = red16(r2); }
            if (tx == 0) {
                atomicAdd(&sSum[0 * N + rowg], e0s);
                atomicAdd(&sSum[1 * N + rowg], e1s);
                atomicAdd(&sSum[2 * N + rowg], e2s);
                atomicAdd(&wSum[0 * N + rowg], w0);
                atomicAdd(&wSum[1 * N + rowg], w1);
                atomicAdd(&wSum[2 * N + rowg], w2);
                atomicAdd(&wSum[3 * N + rowg], w3);
                atomicAdd(&wSum[4 * N + rowg], w4);
                if (rowSum) {
                    atomicAdd(&rowSum[0 * N + rowg], r0);
                    atomicAdd(&rowSum[1 * N + rowg], r1);
                    atomicAdd(&rowSum[2 * N + rowg], r2);
                }
            }
            if (diagDst && I == J && tx == ty) diagDst[rowg] = acc[r][r];
        }
        __syncthreads();
    }
}

__global__ void final_kernel(float* __restrict__ out) {
    const int t = threadIdx.x;  // 256 threads, single block
    const float invT[3] = {1.0f / 0.8f, 1.0f / 0.72f, 1.0f / 0.64f};

    const float* sI1 = g_acc + 0 * N;
    const float* sX12 = g_acc + 3 * N;
    const float* sI2 = g_acc + 6 * N;
    const float* sX21 = g_acc + 9 * N;
    const float* wI1 = g_acc + 12 * N;
    const float* wX12 = g_acc + 17 * N;
    const float* wI2 = g_acc + 22 * N;
    const float* wX21 = g_acc + 27 * N;
    const float* rA = g_acc + 32 * N;
    const float* rG = g_acc + 35 * N;
    const float* d11 = g_acc + 38 * N;
    const float* d22 = g_acc + 39 * N;
    const float* d12 = g_acc + 40 * N;

    float p[13];
#pragma unroll
    for (int k = 0; k < 13; k++) p[k] = 0.0f;

    const int ktau[5] = {0, 0, 0, 2, 1};
    const int kadj1[5] = {0, 1, 2, 0, 1};
    const int kadj2[5] = {0, 1, 2, 2, 2};

    for (int i = t; i < N; i += 256) {
        float e11[3], e22[3], e12[3];
#pragma unroll
        for (int tt = 0; tt < 3; tt++) {
            e11[tt] = expf(d11[i] * invT[tt]);
            e22[tt] = expf(d22[i] * invT[tt]);
            e12[tt] = expf(d12[i] * invT[tt]);
        }
#pragma unroll
        for (int k = 0; k < 5; k++) {
            int tt = ktau[k];
            float pos = e12[tt] + wI1[k * N + i] + wX12[k * N + i];
            float den = sI1[tt * N + i] + sX12[tt * N + i] - e11[tt];
            float cnt = 2.0f * rA[kadj1[k] * N + i] + 1.0f;
            p[k] += logf(pos / den) / cnt;
        }
#pragma unroll
        for (int k = 0; k < 5; k++) {
            int tt = ktau[k];
            float pos = e12[tt] + wI2[k * N + i] + wX21[k * N + i];
            float den = sI2[tt * N + i] + sX21[tt * N + i] - e22[tt];
            float cnt = 2.0f * rG[kadj2[k] * N + i] + 1.0f;
            p[5 + k] += logf(pos / den) / cnt;
        }
        p[10] += rA[0 * N + i];
        p[11] += rA[1 * N + i];
        p[12] += rA[2 * N + i];
    }

    __shared__ float red[256];
    __shared__ float tot[13];
    for (int v = 0; v < 13; v++) {
        red[t] = p[v];
        __syncthreads();
        for (int s = 128; s; s >>= 1) {
            if (t < s) red[t] += red[t + s];
            __syncthreads();
        }
        if (t == 0) tot[v] = red[0];
        __syncthreads();
    }

    if (t == 0) {
        float L1[5], L2[5];
#pragma unroll
        for (int k = 0; k < 5; k++) {
            L1[k] = -tot[k] / (float)N;
            L2[k] = -tot[5 + k] / (float)N;
        }
        float Lc = 0.55f * L1[0] + 0.4f * L2[0];
        float Lm = 0.55f * L1[1] + 0.4f * L2[1];
        float Lf = 0.55f * L1[2] + 0.4f * L2[2];
        float Lcf = 0.55f * L1[3] + 0.4f * L2[3];
        float Lmf = 0.55f * L1[4] + 0.4f * L2[4];
        float sc = tot[10], sm = tot[11], sf = tot[12];
        float total = sc + sm + sf + 1e-8f;
        out[0] = (sc * Lc + sm * Lm + sf * Lf) / total + 0.2f * (Lcf + Lmf);
    }
}

// ---------------- launch ----------------
extern "C" void kernel_launch(void* const* d_in, const int* in_sizes, int n_in,
                              void* d_out, int out_size) {
    const float* z1 = (const float*)d_in[0];
    const float* z2 = (const float*)d_in[1];
    const float* adj_c = (const float*)d_in[2];
    const float* adj_m = (const float*)d_in[3];
    const float* adj_f = (const float*)d_in[4];
    const float* aug_c = (const float*)d_in[5];
    const float* aug_m = (const float*)d_in[6];
    const float* aug_f = (const float*)d_in[7];

    zero_acc_kernel<<<(ACC_TOTAL + 255) / 256, 256>>>();
    normalize_kernel<<<dim3(N, 2), 128>>>(z1, z2);
    gram_kernel<<<dim3(NT, NT), 256>>>(adj_c, adj_m, adj_f, aug_c, aug_m, aug_f);
    final_kernel<<<1, 256>>>((float*)d_out);
}

// round 3
// speedup vs baseline: 1.0284x; 1.0284x over previous
#include <cuda_runtime.h>
#include <math.h>

#define N 4096
#define D 512
#define NT (N / 128)

// ---------------- device scratch (no allocations allowed) ----------------
__device__ float g_zn1[N * D];
__device__ float g_zn2[N * D];

// Accumulator layout (all row-indexed, length N each): see round-2 comment.
#define ACC_TOTAL (41 * N)
__device__ float g_acc[ACC_TOTAL];
__device__ float g_tot[13];

// exp(y) for |y| <= 1.5625 on the FMA pipe only.
// Caller passes q = y * 0.25; result = (poly7(q))^4, rel err ~1e-7.
__device__ __forceinline__ float exp_q4(float q) {
    float p = 1.984127e-4f;                 // 1/5040
    p = fmaf(p, q, 1.3888889e-3f);          // 1/720
    p = fmaf(p, q, 8.3333333e-3f);          // 1/120
    p = fmaf(p, q, 4.1666667e-2f);          // 1/24
    p = fmaf(p, q, 1.6666667e-1f);          // 1/6
    p = fmaf(p, q, 0.5f);
    p = fmaf(p, q, 1.0f);
    p = fmaf(p, q, 1.0f);
    float p2 = p * p;
    return p2 * p2;
}

// ---------------- kernels ----------------
__global__ void zero_acc_kernel() {
    int i = blockIdx.x * blockDim.x + threadIdx.x;
    if (i < ACC_TOTAL) g_acc[i] = 0.0f;
    if (i < 13) g_tot[i] = 0.0f;
}

// One block per row; blockIdx.y selects z1/z2. 128 threads, 4 floats each.
__global__ void normalize_kernel(const float* __restrict__ z1,
                                 const float* __restrict__ z2) {
    int row = blockIdx.x;
    const float* src = (blockIdx.y == 0) ? z1 : z2;
    float* dst = (blockIdx.y == 0) ? g_zn1 : g_zn2;
    int t = threadIdx.x;

    float4 v = ((const float4*)(src + (size_t)row * D))[t];
    float s = v.x * v.x + v.y * v.y + v.z * v.z + v.w * v.w;
#pragma unroll
    for (int o = 16; o; o >>= 1) s += __shfl_xor_sync(0xffffffffu, s, o);

    __shared__ float ws[4];
    if ((t & 31) == 0) ws[t >> 5] = s;
    __syncthreads();
    float tot = ws[0] + ws[1] + ws[2] + ws[3];
    float inv = 1.0f / fmaxf(sqrtf(tot), 1e-12f);
    float4 o4 = make_float4(v.x * inv, v.y * inv, v.z * inv, v.w * inv);
    ((float4*)(dst + (size_t)row * D))[t] = o4;
}

__device__ __forceinline__ float red16(float v) {
#pragma unroll
    for (int o = 8; o; o >>= 1) v += __shfl_xor_sync(0xffffffffu, v, o);
    return v;
}

// 128x128 tile per CTA; 4 sequential Gram passes (S11,S22,S12,S21) with
// fused poly-exp + adjacency-weighted row reductions. No MUFU in hot path.
__global__ __launch_bounds__(256, 2)
void gram_kernel(const float* __restrict__ adj_c, const float* __restrict__ adj_m,
                 const float* __restrict__ adj_f, const float* __restrict__ aug_c,
                 const float* __restrict__ aug_m, const float* __restrict__ aug_f) {
    __shared__ float As[16][128];
    __shared__ float Bs[16][128];

    const int tid = threadIdx.x;
    const int tx = tid & 15;
    const int ty = tid >> 4;
    const int I = blockIdx.y;
    const int J = blockIdx.x;

    // quarter-scaled inverse temperatures (fold the /4 of exp_q4 in here)
    const float QT0 = 0.25f / 0.80f;
    const float QT1 = 0.25f / 0.72f;
    const float QT2 = 0.25f / 0.64f;

    for (int pass = 0; pass < 4; ++pass) {
        const float *A, *B, *a0p, *a1p, *a2p;
        float *sSum, *wSum, *rowSum = nullptr, *diagDst = nullptr;
        bool adjType;
        switch (pass) {
            case 0:
                A = g_zn1; B = g_zn1; a0p = adj_c; a1p = adj_m; a2p = adj_f;
                sSum = g_acc + 0 * N; wSum = g_acc + 12 * N;
                rowSum = g_acc + 32 * N; diagDst = g_acc + 38 * N; adjType = true;
                break;
            case 1:
                A = g_zn2; B = g_zn2; a0p = aug_c; a1p = aug_m; a2p = aug_f;
                sSum = g_acc + 6 * N; wSum = g_acc + 22 * N;
                rowSum = g_acc + 35 * N; diagDst = g_acc + 39 * N; adjType = false;
                break;
            case 2:
                A = g_zn1; B = g_zn2; a0p = adj_c; a1p = adj_m; a2p = adj_f;
                sSum = g_acc + 3 * N; wSum = g_acc + 17 * N;
                diagDst = g_acc + 40 * N; adjType = true;
                break;
            default:
                A = g_zn2; B = g_zn1; a0p = aug_c; a1p = aug_m; a2p = aug_f;
                sSum = g_acc + 9 * N; wSum = g_acc + 27 * N; adjType = false;
                break;
        }

        float acc[8][8];
#pragma unroll
        for (int i = 0; i < 8; i++)
#pragma unroll
            for (int j = 0; j < 8; j++) acc[i][j] = 0.0f;

        const float* Abase = A + (size_t)I * 128 * D;
        const float* Bbase = B + (size_t)J * 128 * D;

        for (int kt = 0; kt < D; kt += 16) {
#pragma unroll
            for (int u = 0; u < 2; u++) {
                int idx = tid + u * 256;          // 0..511 float4 slots
                int row = idx >> 2;               // 0..127
                int c4 = idx & 3;                 // 0..3
                float4 av = *(const float4*)(Abase + (size_t)row * D + kt + c4 * 4);
                As[c4 * 4 + 0][row] = av.x;
                As[c4 * 4 + 1][row] = av.y;
                As[c4 * 4 + 2][row] = av.z;
                As[c4 * 4 + 3][row] = av.w;
                float4 bv = *(const float4*)(Bbase + (size_t)row * D + kt + c4 * 4);
                Bs[c4 * 4 + 0][row] = bv.x;
                Bs[c4 * 4 + 1][row] = bv.y;
                Bs[c4 * 4 + 2][row] = bv.z;
                Bs[c4 * 4 + 3][row] = bv.w;
            }
            __syncthreads();
#pragma unroll
            for (int kk = 0; kk < 16; kk++) {
                float a[8], b[8];
#pragma unroll
                for (int i = 0; i < 8; i++) a[i] = As[kk][ty * 8 + i];
#pragma unroll
                for (int j = 0; j < 8; j++) b[j] = Bs[kk][tx * 8 + j];
#pragma unroll
                for (int i = 0; i < 8; i++)
#pragma unroll
                    for (int j = 0; j < 8; j++) acc[i][j] += a[i] * b[j];
            }
            __syncthreads();
        }

        // ---- fused epilogue: poly exps + adjacency-weighted row reductions ----
        const int rowg0 = I * 128 + ty * 8;
        const int colg0 = J * 128 + tx * 8;
#pragma unroll
        for (int r = 0; r < 8; r++) {
            const int rowg = rowg0 + r;
            const size_t base = (size_t)rowg * N + colg0;
            float a0v[8], a1v[8], a2v[8];
            *(float4*)&a0v[0] = *(const float4*)(a0p + base);
            *(float4*)&a0v[4] = *(const float4*)(a0p + base + 4);
            *(float4*)&a1v[0] = *(const float4*)(a1p + base);
            *(float4*)&a1v[4] = *(const float4*)(a1p + base + 4);
            *(float4*)&a2v[0] = *(const float4*)(a2p + base);
            *(float4*)&a2v[4] = *(const float4*)(a2p + base + 4);

            float e0s = 0.f, e1s = 0.f, e2s = 0.f;
            float w0 = 0.f, w1 = 0.f, w2 = 0.f, w3 = 0.f, w4 = 0.f;
            float r0 = 0.f, r1 = 0.f, r2 = 0.f;
#pragma unroll
            for (int c = 0; c < 8; c++) {
                float s = acc[r][c];
                float e0 = exp_q4(s * QT0);
                float e1 = exp_q4(s * QT1);
                float e2 = exp_q4(s * QT2);
                e0s += e0; e1s += e1; e2s += e2;
                w0 = fmaf(a0v[c], e0, w0);
                w1 = fmaf(a1v[c], e0, w1);
                w2 = fmaf(a2v[c], e0, w2);
                if (adjType) { w3 = fmaf(a0v[c], e2, w3); w4 = fmaf(a1v[c], e1, w4); }
                else         { w3 = fmaf(a2v[c], e2, w3); w4 = fmaf(a2v[c], e1, w4); }
                r0 += a0v[c]; r1 += a1v[c]; r2 += a2v[c];
            }
            e0s = red16(e0s); e1s = red16(e1s); e2s = red16(e2s);
            w0 = red16(w0); w1 = red16(w1); w2 = red16(w2);
            w3 = red16(w3); w4 = red16(w4);
            if (rowSum) { r0 = red16(r0); r1 = red16(r1); r2 = red16(r2); }
            if (tx == 0) {
                atomicAdd(&sSum[0 * N + rowg], e0s);
                atomicAdd(&sSum[1 * N + rowg], e1s);
                atomicAdd(&sSum[2 * N + rowg], e2s);
                atomicAdd(&wSum[0 * N + rowg], w0);
                atomicAdd(&wSum[1 * N + rowg], w1);
                atomicAdd(&wSum[2 * N + rowg], w2);
                atomicAdd(&wSum[3 * N + rowg], w3);
                atomicAdd(&wSum[4 * N + rowg], w4);
                if (rowSum) {
                    atomicAdd(&rowSum[0 * N + rowg], r0);
                    atomicAdd(&rowSum[1 * N + rowg], r1);
                    atomicAdd(&rowSum[2 * N + rowg], r2);
                }
            }
            if (diagDst && I == J && tx == ty) diagDst[rowg] = acc[r][r];
        }
        __syncthreads();
    }
}

// 32 blocks x 128 rows each; partial sums atomically into g_tot[13].
__global__ void final_partial_kernel() {
    const int t = threadIdx.x;  // 128 threads
    const int i0 = blockIdx.x * 128;
    const float invT[3] = {1.0f / 0.8f, 1.0f / 0.72f, 1.0f / 0.64f};

    const float* sI1 = g_acc + 0 * N;
    const float* sX12 = g_acc + 3 * N;
    const float* sI2 = g_acc + 6 * N;
    const float* sX21 = g_acc + 9 * N;
    const float* wI1 = g_acc + 12 * N;
    const float* wX12 = g_acc + 17 * N;
    const float* wI2 = g_acc + 22 * N;
    const float* wX21 = g_acc + 27 * N;
    const float* rA = g_acc + 32 * N;
    const float* rG = g_acc + 35 * N;
    const float* d11 = g_acc + 38 * N;
    const float* d22 = g_acc + 39 * N;
    const float* d12 = g_acc + 40 * N;

    const int ktau[5] = {0, 0, 0, 2, 1};
    const int kadj1[5] = {0, 1, 2, 0, 1};
    const int kadj2[5] = {0, 1, 2, 2, 2};

    float p[13];
#pragma unroll
    for (int k = 0; k < 13; k++) p[k] = 0.0f;

    {
        const int i = i0 + t;
        float e11[3], e22[3], e12[3];
#pragma unroll
        for (int tt = 0; tt < 3; tt++) {
            e11[tt] = expf(d11[i] * invT[tt]);
            e22[tt] = expf(d22[i] * invT[tt]);
            e12[tt] = expf(d12[i] * invT[tt]);
        }
#pragma unroll
        for (int k = 0; k < 5; k++) {
            int tt = ktau[k];
            float pos = e12[tt] + wI1[k * N + i] + wX12[k * N + i];
            float den = sI1[tt * N + i] + sX12[tt * N + i] - e11[tt];
            float cnt = 2.0f * rA[kadj1[k] * N + i] + 1.0f;
            p[k] = logf(pos / den) / cnt;
        }
#pragma unroll
        for (int k = 0; k < 5; k++) {
            int tt = ktau[k];
            float pos = e12[tt] + wI2[k * N + i] + wX21[k * N + i];
            float den = sI2[tt * N + i] + sX21[tt * N + i] - e22[tt];
            float cnt = 2.0f * rG[kadj2[k] * N + i] + 1.0f;
            p[5 + k] = logf(pos / den) / cnt;
        }
        p[10] = rA[0 * N + i];
        p[11] = rA[1 * N + i];
        p[12] = rA[2 * N + i];
    }

    __shared__ float red[128];
#pragma unroll
    for (int v = 0; v < 13; v++) {
        red[t] = p[v];
        __syncthreads();
        for (int s = 64; s; s >>= 1) {
            if (t < s) red[t] += red[t + s];
            __syncthreads();
        }
        if (t == 0) atomicAdd(&g_tot[v], red[0]);
        __syncthreads();
    }
}

__global__ void combine_kernel(float* __restrict__ out) {
    float L1[5], L2[5];
#pragma unroll
    for (int k = 0; k < 5; k++) {
        L1[k] = -g_tot[k] / (float)N;
        L2[k] = -g_tot[5 + k] / (float)N;
    }
    float Lc = 0.55f * L1[0] + 0.4f * L2[0];
    float Lm = 0.55f * L1[1] + 0.4f * L2[1];
    float Lf = 0.55f * L1[2] + 0.4f * L2[2];
    float Lcf = 0.55f * L1[3] + 0.4f * L2[3];
    float Lmf = 0.55f * L1[4] + 0.4f * L2[4];
    float sc = g_tot[10], sm = g_tot[11], sf = g_tot[12];
    float total = sc + sm + sf + 1e-8f;
    out[0] = (sc * Lc + sm * Lm + sf * Lf) / total + 0.2f * (Lcf + Lmf);
}

// ---------------- launch ----------------
extern "C" void kernel_launch(void* const* d_in, const int* in_sizes, int n_in,
                              void* d_out, int out_size) {
    const float* z1 = (const float*)d_in[0];
    const float* z2 = (const float*)d_in[1];
    const float* adj_c = (const float*)d_in[2];
    const float* adj_m = (const float*)d_in[3];
    const float* adj_f = (const float*)d_in[4];
    const float* aug_c = (const float*)d_in[5];
    const float* aug_m = (const float*)d_in[6];
    const float* aug_f = (const float*)d_in[7];

    zero_acc_kernel<<<(ACC_TOTAL + 255) / 256, 256>>>();
    normalize_kernel<<<dim3(N, 2), 128>>>(z1, z2);
    gram_kernel<<<dim3(NT, NT), 256>>>(adj_c, adj_m, adj_f, aug_c, aug_m, aug_f);
    final_partial_kernel<<<32, 128>>>();
    combine_kernel<<<1, 1>>>((float*)d_out);
}

// round 5
// speedup vs baseline: 4.2099x; 4.0937x over previous
#include <cuda_runtime.h>
#include <cuda_fp16.h>
#include <math.h>
#include <stdint.h>

#define N 4096
#define D 512
#define NT (N / 128)

// ---------------- device scratch ----------------
__device__ __half g_h1[N * D];
__device__ __half g_h2[N * D];
__device__ unsigned g_bits[6][N][128];   // bit-packed adjacency (12.6 MB)

// Accumulator layout (row-indexed, length N each):
//  0..2 sI1, 3..5 sX12, 6..8 sI2, 9..11 sX21,
//  12..16 wI1, 17..21 wX12, 22..26 wI2, 27..31 wX21,
//  32..34 rA, 35..37 rG, 38 d11, 39 d22, 40 d12
#define ACC_TOTAL (41 * N)
__device__ float g_acc[ACC_TOTAL];
__device__ float g_tot[13];

// ---------------- smem layout (dynamic) ----------------
#define ABASE 0
#define BBASE 16384
#define CBASE 32768
#define CSTRIDE 132
#define SMEM_BYTES (32768 + 128 * CSTRIDE * 4)   // 100352

#define SWZ(o) ((o) ^ (((o) >> 3) & 0x70))

// ---------------- PTX helpers ----------------
__device__ __forceinline__ uint32_t smem_u32_of(const void* p) {
    uint32_t a;
    asm("{ .reg .u64 t; cvta.to.shared.u64 t, %1; cvt.u32.u64 %0, t; }" : "=r"(a) : "l"(p));
    return a;
}
__device__ __forceinline__ void ldsm4(uint32_t* r, uint32_t addr) {
    asm volatile("ldmatrix.sync.aligned.m8n8.x4.shared.b16 {%0,%1,%2,%3}, [%4];"
                 : "=r"(r[0]), "=r"(r[1]), "=r"(r[2]), "=r"(r[3]) : "r"(addr));
}
__device__ __forceinline__ void mma16816(float* c, const uint32_t* a, const uint32_t* b) {
    asm volatile(
        "mma.sync.aligned.m16n8k16.row.col.f32.f16.f16.f32 "
        "{%0,%1,%2,%3}, {%4,%5,%6,%7}, {%8,%9}, {%0,%1,%2,%3};"
        : "+f"(c[0]), "+f"(c[1]), "+f"(c[2]), "+f"(c[3])
        : "r"(a[0]), "r"(a[1]), "r"(a[2]), "r"(a[3]), "r"(b[0]), "r"(b[1]));
}

// ---------------- fast exp (FMA pipe only) ----------------
__device__ __forceinline__ float exp_q4(float q) {   // exp(4q), |q|<=0.4
    float p = 1.984127e-4f;
    p = fmaf(p, q, 1.3888889e-3f);
    p = fmaf(p, q, 8.3333333e-3f);
    p = fmaf(p, q, 4.1666667e-2f);
    p = fmaf(p, q, 1.6666667e-1f);
    p = fmaf(p, q, 0.5f);
    p = fmaf(p, q, 1.0f);
    p = fmaf(p, q, 1.0f);
    float p2 = p * p;
    return p2 * p2;
}
__device__ __forceinline__ float exp_small(float y) { // exp(y), |y|<=0.35
    float p = 1.3888889e-3f;
    p = fmaf(p, y, 8.3333333e-3f);
    p = fmaf(p, y, 4.1666667e-2f);
    p = fmaf(p, y, 1.6666667e-1f);
    p = fmaf(p, y, 0.5f);
    p = fmaf(p, y, 1.0f);
    p = fmaf(p, y, 1.0f);
    return p;
}

// ---------------- small kernels ----------------
__global__ void zero_acc_kernel() {
    int i = blockIdx.x * blockDim.x + threadIdx.x;
    if (i < ACC_TOTAL) g_acc[i] = 0.0f;
    if (i < 13) g_tot[i] = 0.0f;
}

// Bit-pack adjacency + row sums. grid(N, 6), block 128.
__global__ void pack_adj_kernel(const float* __restrict__ a0, const float* __restrict__ a1,
                                const float* __restrict__ a2, const float* __restrict__ a3,
                                const float* __restrict__ a4, const float* __restrict__ a5) {
    const int row = blockIdx.x, mat = blockIdx.y, t = threadIdx.x;
    const float* src;
    switch (mat) {
        case 0: src = a0; break; case 1: src = a1; break; case 2: src = a2; break;
        case 3: src = a3; break; case 4: src = a4; break; default: src = a5; break;
    }
    const int lane = t & 31, w = t >> 5;
    int cnt = 0;
    for (int it = 0; it < 32; it++) {
        float v = src[(size_t)row * N + it * 128 + t];
        unsigned bal = __ballot_sync(0xffffffffu, v != 0.0f);
        if (lane == 0) { g_bits[mat][row][it * 4 + w] = bal; cnt += __popc(bal); }
    }
    __shared__ int sc[4];
    if (lane == 0) sc[w] = cnt;
    __syncthreads();
    if (t == 0)
        g_acc[(32 + mat) * N + row] = (float)(sc[0] + sc[1] + sc[2] + sc[3]);
}

// Normalize fp32 -> fp16. grid(N,2), block 128.
__global__ void normalize_kernel(const float* __restrict__ z1,
                                 const float* __restrict__ z2) {
    int row = blockIdx.x;
    const float* src = (blockIdx.y == 0) ? z1 : z2;
    __half* dst = (blockIdx.y == 0) ? g_h1 : g_h2;
    int t = threadIdx.x;

    float4 v = ((const float4*)(src + (size_t)row * D))[t];
    float s = v.x * v.x + v.y * v.y + v.z * v.z + v.w * v.w;
#pragma unroll
    for (int o = 16; o; o >>= 1) s += __shfl_xor_sync(0xffffffffu, s, o);
    __shared__ float ws[4];
    if ((t & 31) == 0) ws[t >> 5] = s;
    __syncthreads();
    float inv = 1.0f / fmaxf(sqrtf(ws[0] + ws[1] + ws[2] + ws[3]), 1e-12f);
    size_t base = (size_t)row * D + t * 4;
    dst[base + 0] = __float2half_rn(v.x * inv);
    dst[base + 1] = __float2half_rn(v.y * inv);
    dst[base + 2] = __float2half_rn(v.z * inv);
    dst[base + 3] = __float2half_rn(v.w * inv);
}

// ---------------- gram kernel: fp16 mma.sync, 4 fused passes ----------------
__global__ void __launch_bounds__(256, 1) gram_kernel() {
    extern __shared__ char smem[];
    float* Cs = (float*)(smem + CBASE);
    const uint32_t sb = smem_u32_of(smem);
    const int tid = threadIdx.x, lane = tid & 31, wid = tid >> 5;
    const int wm = wid & 1, wn = wid >> 1;   // warp tile: rows wm*64, cols wn*32
    const int I = blockIdx.y, J = blockIdx.x;

    // ldmatrix per-lane addressing components
    const int arow = wm * 64 + (lane & 15);            // + mt*16
    const int akb0 = (lane >> 4) * 16;                 // + ks*32
    const int brow = wn * 32 + ((lane >> 4) * 8) + (lane & 7);  // + ntp*16
    const int bkb0 = ((lane >> 3) & 1) * 16;           // + ks*32

    // staging address components (u = tid + i*256 -> row, seg)
    const int sbases[4][2] = {
        {(tid + 0) >> 3, (tid + 0) & 7}, {(tid + 256) >> 3, (tid + 256) & 7},
        {(tid + 512) >> 3, (tid + 512) & 7}, {(tid + 768) >> 3, (tid + 768) & 7}};

    const int sOff[4] = {0, 6, 3, 9};
    const int wOff[4] = {12, 22, 17, 27};

    for (int pass = 0; pass < 4; ++pass) {
        const __half *Ap, *Bp;
        switch (pass) {
            case 0: Ap = g_h1; Bp = g_h1; break;
            case 1: Ap = g_h2; Bp = g_h2; break;
            case 2: Ap = g_h1; Bp = g_h2; break;
            default: Ap = g_h2; Bp = g_h1; break;
        }
        const __half* Ag = Ap + (size_t)I * 128 * D;
        const __half* Bg = Bp + (size_t)J * 128 * D;

        float cfr[16][4];
#pragma unroll
        for (int i = 0; i < 16; i++)
#pragma unroll
            for (int j = 0; j < 4; j++) cfr[i][j] = 0.0f;

        uint4 ra[4], rb[4];
#pragma unroll
        for (int i = 0; i < 4; i++) {
            ra[i] = *(const uint4*)(Ag + (size_t)sbases[i][0] * D + sbases[i][1] * 8);
            rb[i] = *(const uint4*)(Bg + (size_t)sbases[i][0] * D + sbases[i][1] * 8);
        }

        for (int kc = 0; kc < 8; ++kc) {
            // commit staged regs to smem (SW128 swizzle)
#pragma unroll
            for (int i = 0; i < 4; i++) {
                uint32_t off = SWZ((uint32_t)(sbases[i][0] * 128 + sbases[i][1] * 16));
                *(uint4*)(smem + ABASE + off) = ra[i];
                *(uint4*)(smem + BBASE + off) = rb[i];
            }
            __syncthreads();
            // stage next chunk
            if (kc < 7) {
#pragma unroll
                for (int i = 0; i < 4; i++) {
                    const size_t g = (size_t)sbases[i][0] * D + (kc + 1) * 64 + sbases[i][1] * 8;
                    ra[i] = *(const uint4*)(Ag + g);
                    rb[i] = *(const uint4*)(Bg + g);
                }
            }
            // 4 k16 steps of mma
#pragma unroll
            for (int ks = 0; ks < 4; ++ks) {
                uint32_t af[16], bf[8];
#pragma unroll
                for (int mt = 0; mt < 4; mt++) {
                    uint32_t off = SWZ((uint32_t)((arow + mt * 16) * 128 + ks * 32 + akb0));
                    ldsm4(&af[mt * 4], sb + ABASE + off);
                }
#pragma unroll
                for (int ntp = 0; ntp < 2; ntp++) {
                    uint32_t off = SWZ((uint32_t)((brow + ntp * 16) * 128 + ks * 32 + bkb0));
                    ldsm4(&bf[ntp * 4], sb + BBASE + off);
                }
#pragma unroll
                for (int mt = 0; mt < 4; mt++)
#pragma unroll
                    for (int nt = 0; nt < 4; nt++)
                        mma16816(cfr[mt * 4 + nt], &af[mt * 4], &bf[nt * 2]);
            }
            __syncthreads();
        }

        // ---- dump C fragments to smem ----
#pragma unroll
        for (int mt = 0; mt < 4; mt++) {
            int row0 = wm * 64 + mt * 16 + (lane >> 2);
#pragma unroll
            for (int nt = 0; nt < 4; nt++) {
                int col = wn * 32 + nt * 8 + (lane & 3) * 2;
                *(float2*)&Cs[row0 * CSTRIDE + col] =
                    make_float2(cfr[mt * 4 + nt][0], cfr[mt * 4 + nt][1]);
                *(float2*)&Cs[(row0 + 8) * CSTRIDE + col] =
                    make_float2(cfr[mt * 4 + nt][2], cfr[mt * 4 + nt][3]);
            }
        }
        __syncthreads();

        // ---- epilogue: thread pair (t, t^1) owns row r = tid>>1 ----
        {
            const int r = tid >> 1, h = tid & 1;
            const int rowg = I * 128 + r;
            const bool adjType = (pass == 0 || pass == 2);
            const int mbase = adjType ? 0 : 3;
            const int wword = J * 4 + h * 2;
            unsigned m0[2], m1[2], m2[2];
            m0[0] = g_bits[mbase + 0][rowg][wword];
            m0[1] = g_bits[mbase + 0][rowg][wword + 1];
            m1[0] = g_bits[mbase + 1][rowg][wword];
            m1[1] = g_bits[mbase + 1][rowg][wword + 1];
            m2[0] = g_bits[mbase + 2][rowg][wword];
            m2[1] = g_bits[mbase + 2][rowg][wword + 1];

            float s0 = 0, s1 = 0, s2 = 0, w0 = 0, w1 = 0, w2 = 0, w3 = 0, w4 = 0;
            const float* crow = &Cs[r * CSTRIDE + h * 64];
#pragma unroll
            for (int hw = 0; hw < 2; hw++) {
                const unsigned ma = m0[hw], mb = m1[hw], mc = m2[hw];
#pragma unroll
                for (int b = 0; b < 32; b++) {
                    float s = crow[hw * 32 + b];
                    float e0 = exp_q4(s * 0.3125f);
                    float e1 = e0 * exp_small(s * 0.13888889f);
                    float e2 = e0 * exp_small(s * 0.3125f);
                    s0 += e0; s1 += e1; s2 += e2;
                    if ((ma >> b) & 1) { w0 += e0; if (adjType) w3 += e2; }
                    if ((mb >> b) & 1) { w1 += e0; if (adjType) w4 += e1; }
                    if ((mc >> b) & 1) { w2 += e0; if (!adjType) { w3 += e2; w4 += e1; } }
                }
            }
            if (I == J && h == 0 && pass < 3) {
                float dv = Cs[r * CSTRIDE + r];
                if (pass == 0) g_acc[38 * N + rowg] = dv;
                else if (pass == 1) g_acc[39 * N + rowg] = dv;
                else g_acc[40 * N + rowg] = dv;
            }
            // pair combine
            s0 += __shfl_xor_sync(0xffffffffu, s0, 1);
            s1 += __shfl_xor_sync(0xffffffffu, s1, 1);
            s2 += __shfl_xor_sync(0xffffffffu, s2, 1);
            w0 += __shfl_xor_sync(0xffffffffu, w0, 1);
            w1 += __shfl_xor_sync(0xffffffffu, w1, 1);
            w2 += __shfl_xor_sync(0xffffffffu, w2, 1);
            w3 += __shfl_xor_sync(0xffffffffu, w3, 1);
            w4 += __shfl_xor_sync(0xffffffffu, w4, 1);
            if (h == 0) {
                const int so = sOff[pass], wo = wOff[pass];
                atomicAdd(&g_acc[(so + 0) * N + rowg], s0);
                atomicAdd(&g_acc[(so + 1) * N + rowg], s1);
                atomicAdd(&g_acc[(so + 2) * N + rowg], s2);
                atomicAdd(&g_acc[(wo + 0) * N + rowg], w0);
                atomicAdd(&g_acc[(wo + 1) * N + rowg], w1);
                atomicAdd(&g_acc[(wo + 2) * N + rowg], w2);
                atomicAdd(&g_acc[(wo + 3) * N + rowg], w3);
                atomicAdd(&g_acc[(wo + 4) * N + rowg], w4);
            }
        }
        __syncthreads();
    }
}

// ---------------- final reduction ----------------
__global__ void final_partial_kernel() {
    const int t = threadIdx.x;  // 128
    const int i = blockIdx.x * 128 + t;
    const float invT[3] = {1.0f / 0.8f, 1.0f / 0.72f, 1.0f / 0.64f};

    const float* sI1 = g_acc + 0 * N;  const float* sX12 = g_acc + 3 * N;
    const float* sI2 = g_acc + 6 * N;  const float* sX21 = g_acc + 9 * N;
    const float* wI1 = g_acc + 12 * N; const float* wX12 = g_acc + 17 * N;
    const float* wI2 = g_acc + 22 * N; const float* wX21 = g_acc + 27 * N;
    const float* rA = g_acc + 32 * N;  const float* rG = g_acc + 35 * N;
    const float* d11 = g_acc + 38 * N; const float* d22 = g_acc + 39 * N;
    const float* d12 = g_acc + 40 * N;

    const int ktau[5] = {0, 0, 0, 2, 1};
    const int kadj1[5] = {0, 1, 2, 0, 1};
    const int kadj2[5] = {0, 1, 2, 2, 2};

    float p[13];
    {
        float e11[3], e22[3], e12[3];
#pragma unroll
        for (int tt = 0; tt < 3; tt++) {
            e11[tt] = expf(d11[i] * invT[tt]);
            e22[tt] = expf(d22[i] * invT[tt]);
            e12[tt] = expf(d12[i] * invT[tt]);
        }
#pragma unroll
        for (int k = 0; k < 5; k++) {
            int tt = ktau[k];
            float pos = e12[tt] + wI1[k * N + i] + wX12[k * N + i];
            float den = sI1[tt * N + i] + sX12[tt * N + i] - e11[tt];
            p[k] = logf(pos / den) / (2.0f * rA[kadj1[k] * N + i] + 1.0f);
        }
#pragma unroll
        for (int k = 0; k < 5; k++) {
            int tt = ktau[k];
            float pos = e12[tt] + wI2[k * N + i] + wX21[k * N + i];
            float den = sI2[tt * N + i] + sX21[tt * N + i] - e22[tt];
            p[5 + k] = logf(pos / den) / (2.0f * rG[kadj2[k] * N + i] + 1.0f);
        }
        p[10] = rA[0 * N + i]; p[11] = rA[1 * N + i]; p[12] = rA[2 * N + i];
    }

    __shared__ float red[128];
#pragma unroll
    for (int v = 0; v < 13; v++) {
        red[t] = p[v];
        __syncthreads();
        for (int s = 64; s; s >>= 1) {
            if (t < s) red[t] += red[t + s];
            __syncthreads();
        }
        if (t == 0) atomicAdd(&g_tot[v], red[0]);
        __syncthreads();
    }
}

__global__ void combine_kernel(float* __restrict__ out) {
    float L1[5], L2[5];
#pragma unroll
    for (int k = 0; k < 5; k++) {
        L1[k] = -g_tot[k] / (float)N;
        L2[k] = -g_tot[5 + k] / (float)N;
    }
    float Lc = 0.55f * L1[0] + 0.4f * L2[0];
    float Lm = 0.55f * L1[1] + 0.4f * L2[1];
    float Lf = 0.55f * L1[2] + 0.4f * L2[2];
    float Lcf = 0.55f * L1[3] + 0.4f * L2[3];
    float Lmf = 0.55f * L1[4] + 0.4f * L2[4];
    float sc = g_tot[10], sm = g_tot[11], sf = g_tot[12];
    float total = sc + sm + sf + 1e-8f;
    out[0] = (sc * Lc + sm * Lm + sf * Lf) / total + 0.2f * (Lcf + Lmf);
}

// ---------------- launch ----------------
extern "C" void kernel_launch(void* const* d_in, const int* in_sizes, int n_in,
                              void* d_out, int out_size) {
    const float* z1 = (const float*)d_in[0];
    const float* z2 = (const float*)d_in[1];

    cudaFuncSetAttribute(gram_kernel, cudaFuncAttributeMaxDynamicSharedMemorySize,
                         SMEM_BYTES);

    zero_acc_kernel<<<(ACC_TOTAL + 255) / 256, 256>>>();
    pack_adj_kernel<<<dim3(N, 6), 128>>>(
        (const float*)d_in[2], (const float*)d_in[3], (const float*)d_in[4],
        (const float*)d_in[5], (const float*)d_in[6], (const float*)d_in[7]);
    normalize_kernel<<<dim3(N, 2), 128>>>(z1, z2);
    gram_kernel<<<dim3(NT, NT), 256, SMEM_BYTES>>>();
    final_partial_kernel<<<32, 128>>>();
    combine_kernel<<<1, 1>>>((float*)d_out);
}